// round 4
// baseline (speedup 1.0000x reference)
#include <cuda_runtime.h>
#include <cuda_bf16.h>

#define SEQ_LEN 512
#define BATCH   256
#define CAUSES  64
#define STATES  512
#define OUT_DIM 256
#define RPC     4      // batch rows per CTA
#define NCTA    (BATCH / RPC)
#define NT      256

#define INV_TAU 0.1f
#define ALPHA_X 0.1f
#define ALPHA_H 0.1f

typedef unsigned long long u64;

// ---- transposed weight scratch (device globals: allocation-free) ----
__device__ float g_wrT[STATES * STATES];   // g_wrT[k*512 + j] = w_r[j*512 + k]
__device__ float g_woT[STATES * OUT_DIM];  // g_woT[j*256 + o] = w_o[o*512 + j]
__device__ float g_wcT[CAUSES * STATES];   // g_wcT[m*512 + j] = w_c[j*64  + m]

// ---- packed f32x2 helpers (must be PTX; ptxas won't auto-fuse) ----
__device__ __forceinline__ u64 dup2(float s) {
    u64 r; asm("mov.b64 %0, {%1, %1};" : "=l"(r) : "f"(s)); return r;
}
__device__ __forceinline__ u64 pack2(float a, float b) {
    u64 r; asm("mov.b64 %0, {%1, %2};" : "=l"(r) : "f"(a), "f"(b)); return r;
}
__device__ __forceinline__ void fma2(u64& d, u64 a, u64 b) {
    asm("fma.rn.f32x2 %0, %1, %2, %3;" : "=l"(d) : "l"(a), "l"(b), "l"(d));
}
__device__ __forceinline__ void unpack2(u64 v, float& lo, float& hi) {
    asm("mov.b64 {%0, %1}, %2;" : "=f"(lo), "=f"(hi) : "l"(v));
}

// ---- prologue: 32x32 tiled transposes into the device globals ----
__device__ __forceinline__ void transpose_tile(float* __restrict__ out,
                                               const float* __restrict__ in,
                                               int R, int C) {
    __shared__ float tile[32][33];
    int rb = blockIdx.y * 32, cb = blockIdx.x * 32;
    tile[threadIdx.y][threadIdx.x] = in[(size_t)(rb + threadIdx.y) * C + cb + threadIdx.x];
    __syncthreads();
    out[(size_t)(cb + threadIdx.y) * R + rb + threadIdx.x] = tile[threadIdx.x][threadIdx.y];
}

__global__ void t_wr(const float* __restrict__ in) { transpose_tile(g_wrT, in, STATES, STATES); }
__global__ void t_wo(const float* __restrict__ in) { transpose_tile(g_woT, in, OUT_DIM, STATES); }
__global__ void t_wc(const float* __restrict__ in) { transpose_tile(g_wcT, in, STATES, CAUSES); }

// ---- main persistent recurrence kernel ----
__global__ __launch_bounds__(NT, 1)
void pc_rnn_kernel(const float* __restrict__ x,
                   const float* __restrict__ c_init,
                   const float* __restrict__ h_init,
                   const float* __restrict__ w_o,
                   const float* __restrict__ b_o,
                   const float* __restrict__ w_c,
                   const float* __restrict__ b_r,
                   float* __restrict__ out)
{
    // smem: dup'd = each entry is a b64 with the float in both halves
    __shared__ u64   s_th2 [STATES  * RPC];  // tanh(h)      [k][r]  dup'd  16KB
    __shared__ float s_tp4 [STATES  * RPC];  // tanh(hprior) [j][r]  plain   8KB
    __shared__ u64   s_err2[OUT_DIM * RPC];  // error        [o][r]  dup'd   8KB
    __shared__ float s_eh4 [STATES  * RPC];  // error_h      [j][r]  plain   8KB
    __shared__ u64   s_c2  [CAUSES  * RPC];  // c            [m][r]  dup'd   2KB

    const int tid = threadIdx.x;
    const int b0  = blockIdx.x * RPC;
    const int j0  = tid * 2;           // this thread's state pair (j0, j0+1)

    float h[RPC][2], hp[RPC][2], tp[RPC][2];
#pragma unroll
    for (int r = 0; r < RPC; ++r) {
        h[r][0] = h_init[(size_t)(b0 + r) * STATES + j0];
        h[r][1] = h_init[(size_t)(b0 + r) * STATES + j0 + 1];
    }
    const float rb0 = b_r[j0], rb1 = b_r[j0 + 1];
    const float rbo = b_o[tid];        // o = tid in phase C

    // c ownership: (m = tid & 63, r = tid >> 6), one scalar per thread
    const int cm = tid & 63, cr = tid >> 6;
    float creg = c_init[(size_t)(b0 + cr) * CAUSES + cm];
    s_c2[cm * RPC + cr] = dup2(creg);
    __syncthreads();

    for (int t = 0; t < SEQ_LEN; ++t) {
        // ---------- Phase A: th = tanh(h), dup'd into smem ----------
#pragma unroll
        for (int r = 0; r < RPC; ++r) {
            s_th2[(j0)     * RPC + r] = dup2(tanhf(h[r][0]));
            s_th2[(j0 + 1) * RPC + r] = dup2(tanhf(h[r][1]));
        }
        __syncthreads();

        // ---------- Phase B: h_prior = (1-1/tau)h + (1/tau)(th@WrT + c@WcT + b_r) ----------
        u64 acc[RPC];
#pragma unroll
        for (int r = 0; r < RPC; ++r) acc[r] = 0ULL;

#pragma unroll 4
        for (int k = 0; k < STATES; ++k) {
            u64 w2 = *(const u64*)(g_wrT + (size_t)k * STATES + j0);
            ulonglong2 t01 = *(const ulonglong2*)&s_th2[k * RPC];
            ulonglong2 t23 = *(const ulonglong2*)&s_th2[k * RPC + 2];
            fma2(acc[0], t01.x, w2);
            fma2(acc[1], t01.y, w2);
            fma2(acc[2], t23.x, w2);
            fma2(acc[3], t23.y, w2);
        }
#pragma unroll 4
        for (int m = 0; m < CAUSES; ++m) {
            u64 w2 = *(const u64*)(g_wcT + (size_t)m * STATES + j0);
            ulonglong2 c01 = *(const ulonglong2*)&s_c2[m * RPC];
            ulonglong2 c23 = *(const ulonglong2*)&s_c2[m * RPC + 2];
            fma2(acc[0], c01.x, w2);
            fma2(acc[1], c01.y, w2);
            fma2(acc[2], c23.x, w2);
            fma2(acc[3], c23.y, w2);
        }
        {
            float tpv0[RPC], tpv1[RPC];
#pragma unroll
            for (int r = 0; r < RPC; ++r) {
                float a0, a1; unpack2(acc[r], a0, a1);
                hp[r][0] = (1.0f - INV_TAU) * h[r][0] + INV_TAU * (a0 + rb0);
                hp[r][1] = (1.0f - INV_TAU) * h[r][1] + INV_TAU * (a1 + rb1);
                tp[r][0] = tanhf(hp[r][0]);
                tp[r][1] = tanhf(hp[r][1]);
                tpv0[r] = tp[r][0]; tpv1[r] = tp[r][1];
            }
            *(float4*)&s_tp4[(j0)     * RPC] = make_float4(tpv0[0], tpv0[1], tpv0[2], tpv0[3]);
            *(float4*)&s_tp4[(j0 + 1) * RPC] = make_float4(tpv1[0], tpv1[1], tpv1[2], tpv1[3]);
        }
        __syncthreads();

        // ---------- Phase C: x_pred = tp@WoT + b_o ; err = x_pred - x_t ----------
        {
            const int o = tid;
            u64 e01 = 0ULL, e23 = 0ULL;   // rows (0,1) and (2,3) packed
#pragma unroll 4
            for (int j = 0; j < STATES; ++j) {
                float4 tpv = *(const float4*)&s_tp4[j * RPC];
                u64 wd = dup2(g_woT[(size_t)j * OUT_DIM + o]);
                fma2(e01, pack2(tpv.x, tpv.y), wd);
                fma2(e23, pack2(tpv.z, tpv.w), wd);
            }
            float p0, p1, p2, p3;
            unpack2(e01, p0, p1); unpack2(e23, p2, p3);
            float er[RPC];
            er[0] = (p0 + rbo) - x[((size_t)t * BATCH + b0 + 0) * OUT_DIM + o];
            er[1] = (p1 + rbo) - x[((size_t)t * BATCH + b0 + 1) * OUT_DIM + o];
            er[2] = (p2 + rbo) - x[((size_t)t * BATCH + b0 + 2) * OUT_DIM + o];
            er[3] = (p3 + rbo) - x[((size_t)t * BATCH + b0 + 3) * OUT_DIM + o];
#pragma unroll
            for (int r = 0; r < RPC; ++r) {
                out[((size_t)t * BATCH + b0 + r) * OUT_DIM + o] = er[r];
                s_err2[o * RPC + r] = dup2(er[r]);
            }
        }
        __syncthreads();

        // ---------- Phase D: h_post = hp - ax*(1-tp^2)*(err@Wo) ; eh to smem ----------
        {
            u64 g[RPC];
#pragma unroll
            for (int r = 0; r < RPC; ++r) g[r] = 0ULL;
#pragma unroll 4
            for (int o = 0; o < OUT_DIM; ++o) {
                u64 w2 = *(const u64*)(w_o + (size_t)o * STATES + j0);
                ulonglong2 e01 = *(const ulonglong2*)&s_err2[o * RPC];
                ulonglong2 e23 = *(const ulonglong2*)&s_err2[o * RPC + 2];
                fma2(g[0], e01.x, w2);
                fma2(g[1], e01.y, w2);
                fma2(g[2], e23.x, w2);
                fma2(g[3], e23.y, w2);
            }
            float eh0[RPC], eh1[RPC];
#pragma unroll
            for (int r = 0; r < RPC; ++r) {
                float g0, g1; unpack2(g[r], g0, g1);
                float d0 = ALPHA_X * (1.0f - tp[r][0] * tp[r][0]) * g0;
                float d1 = ALPHA_X * (1.0f - tp[r][1] * tp[r][1]) * g1;
                h[r][0] = hp[r][0] - d0;
                h[r][1] = hp[r][1] - d1;
                eh0[r] = d0; eh1[r] = d1;
            }
            *(float4*)&s_eh4[(j0)     * RPC] = make_float4(eh0[0], eh0[1], eh0[2], eh0[3]);
            *(float4*)&s_eh4[(j0 + 1) * RPC] = make_float4(eh1[0], eh1[1], eh1[2], eh1[3]);
        }
        __syncthreads();

        // ---------- Phase E: c -= ah * (eh @ Wc) ; thread (cm, cr) ----------
        {
            float ca = 0.0f;
#pragma unroll 8
            for (int j = 0; j < STATES; ++j)
                ca += s_eh4[j * RPC + cr] * w_c[(size_t)j * CAUSES + cm];
            creg = creg - ALPHA_H * ca;
            s_c2[cm * RPC + cr] = dup2(creg);
        }
        __syncthreads();
    }
}

extern "C" void kernel_launch(void* const* d_in, const int* in_sizes, int n_in,
                              void* d_out, int out_size) {
    const float* x      = (const float*)d_in[0];
    const float* c_init = (const float*)d_in[1];
    const float* h_init = (const float*)d_in[2];
    const float* w_o    = (const float*)d_in[3];
    const float* b_o    = (const float*)d_in[4];
    const float* w_c    = (const float*)d_in[5];
    const float* w_r    = (const float*)d_in[6];
    const float* b_r    = (const float*)d_in[7];
    float* out          = (float*)d_out;

    dim3 tb(32, 32);
    t_wr<<<dim3(STATES / 32,  STATES  / 32), tb>>>(w_r);   // 512x512 -> g_wrT
    t_wo<<<dim3(STATES / 32,  OUT_DIM / 32), tb>>>(w_o);   // 256x512 -> g_woT
    t_wc<<<dim3(CAUSES / 32,  STATES  / 32), tb>>>(w_c);   // 512x64  -> g_wcT

    pc_rnn_kernel<<<NCTA, NT>>>(x, c_init, h_init, w_o, b_o, w_c, b_r, out);
}

// round 5
// speedup vs baseline: 1.3688x; 1.3688x over previous
#include <cuda_runtime.h>
#include <cuda_bf16.h>

#define SEQ_LEN 512
#define BATCH   256
#define CAUSES  64
#define STATES  512
#define OUT_DIM 256
#define RPC     4
#define NCTA    (BATCH / RPC)
#define NT      256

#define ALPHA_X 0.1f
#define ALPHA_H 0.1f

typedef unsigned long long u64;

// ---------------- packed weight scratch (device globals: allocation-free) ----
// wrP: [k2][jp][4] = {wr[j0][k],wr[j0+1][k],wr[j0][k+1],wr[j0+1][k+1]}  (k=2*k2, j0=2*jp)
__device__ float g_wrP[STATES/2 * STATES * 2];            // 256*1024 = 262144
// wcB: same pattern over m:  {wc[j0][m],wc[j0+1][m],wc[j0][m+1],wc[j0+1][m+1]}
__device__ float g_wcB[CAUSES/2 * STATES * 2];            // 32*1024  = 32768
// woC: [j4][o][4] = {wo[o][j4*4+0..3]}
__device__ float g_woC[STATES/4 * OUT_DIM * 4];           // 128*1024 = 131072
// woD: [o2][jp][4] = {wo[o][j0],wo[o][j0+1],wo[o+1][j0],wo[o+1][j0+1]}
__device__ float g_woD[OUT_DIM/2 * STATES * 2];           // 128*1024 = 131072
// wcE: [j2][m][2] = {wc[2*j2][m], wc[2*j2+1][m]}
__device__ float g_wcE[STATES/2 * CAUSES * 2];            // 256*128  = 32768

// ---------------- packed f32x2 helpers (PTX; ptxas won't auto-fuse) ----
__device__ __forceinline__ u64 dup2(float s) {
    u64 r; asm("mov.b64 %0, {%1, %1};" : "=l"(r) : "f"(s)); return r;
}
__device__ __forceinline__ u64 pack2(float a, float b) {
    u64 r; asm("mov.b64 %0, {%1, %2};" : "=l"(r) : "f"(a), "f"(b)); return r;
}
__device__ __forceinline__ void fma2(u64& d, u64 a, u64 b) {
    asm("fma.rn.f32x2 %0, %1, %2, %3;" : "=l"(d) : "l"(a), "l"(b), "l"(d));
}
__device__ __forceinline__ void unpack2(u64 v, float& lo, float& hi) {
    asm("mov.b64 {%0, %1}, %2;" : "=f"(lo), "=f"(hi) : "l"(v));
}

// ---------------- prologue pack kernels (run once per launch; ~µs) ----------
__global__ void pack_wrB(const float* __restrict__ w) {        // w_r [512][512]
    int idx = blockIdx.x * 256 + threadIdx.x;                  // 262144
    int k2 = idx >> 10, rem = idx & 1023;
    int jp = rem >> 2, c = rem & 3;
    int j = jp * 2 + (c & 1), k = k2 * 2 + (c >> 1);
    g_wrP[idx] = w[j * STATES + k];
}
__global__ void pack_wcB(const float* __restrict__ w) {        // w_c [512][64]
    int idx = blockIdx.x * 256 + threadIdx.x;                  // 32768
    int m2 = idx >> 10, rem = idx & 1023;
    int jp = rem >> 2, c = rem & 3;
    int j = jp * 2 + (c & 1), m = m2 * 2 + (c >> 1);
    g_wcB[idx] = w[j * CAUSES + m];
}
__global__ void pack_woC(const float* __restrict__ w) {        // w_o [256][512]
    int idx = blockIdx.x * 256 + threadIdx.x;                  // 131072
    int j4 = idx >> 10, rem = idx & 1023;
    int o = rem >> 2, jj = rem & 3;
    g_woC[idx] = w[o * STATES + j4 * 4 + jj];
}
__global__ void pack_woD(const float* __restrict__ w) {        // w_o [256][512]
    int idx = blockIdx.x * 256 + threadIdx.x;                  // 131072
    int o2 = idx >> 10, rem = idx & 1023;
    int jp = rem >> 2, c = rem & 3;
    int j = jp * 2 + (c & 1), o = o2 * 2 + (c >> 1);
    g_woD[idx] = w[o * STATES + j];
}
__global__ void pack_wcE(const float* __restrict__ w) {        // w_c [512][64]
    int idx = blockIdx.x * 256 + threadIdx.x;                  // 32768
    int j2 = idx >> 7, rem = idx & 127;
    int m = rem >> 1, jj = rem & 1;
    g_wcE[idx] = w[(j2 * 2 + jj) * CAUSES + m];
}

// ---------------- main persistent recurrence kernel ----------
__global__ __launch_bounds__(NT, 1)
void pc_rnn_kernel(const float* __restrict__ x,
                   const float* __restrict__ c_init,
                   const float* __restrict__ h_init,
                   const float* __restrict__ b_o,
                   const float* __restrict__ b_r,
                   float* __restrict__ out)
{
    __shared__ u64 s_th2 [STATES  * RPC];     // tanh(h_post) dup'd  [k][r]   16KB
    __shared__ u64 s_tp2 [STATES  * 2];       // tanh(h_prior) pairs [j][rp]   8KB
    __shared__ u64 s_err2[OUT_DIM * RPC];     // error dup'd         [o][r]    8KB
    __shared__ u64 s_eh2 [(STATES/2) * RPC];  // error_h j-pairs     [j2][r]   8KB
    __shared__ u64 s_c2  [CAUSES  * RPC];     // c dup'd             [m][r]    2KB

    const int tid = threadIdx.x;
    const int b0  = blockIdx.x * RPC;
    const int j0  = tid * 2;

    float h0[RPC], h1[RPC], hp0[RPC], hp1[RPC], tp0[RPC], tp1[RPC];
#pragma unroll
    for (int r = 0; r < RPC; ++r) {
        h0[r] = h_init[(size_t)(b0 + r) * STATES + j0];
        h1[r] = h_init[(size_t)(b0 + r) * STATES + j0 + 1];
    }
    const float rb0 = b_r[j0], rb1 = b_r[j0 + 1];
    const float rbo = b_o[tid];

    const int cm = tid & 63, cr = tid >> 6;
    float creg = c_init[(size_t)(b0 + cr) * CAUSES + cm];
    s_c2[cm * RPC + cr] = dup2(creg);
#pragma unroll
    for (int r = 0; r < RPC; ++r) {
        s_th2[(j0)     * RPC + r] = dup2(tanhf(h0[r]));
        s_th2[(j0 + 1) * RPC + r] = dup2(tanhf(h1[r]));
    }
    __syncthreads();

    const float4* __restrict__ wrB = (const float4*)g_wrP;
    const float4* __restrict__ wcB = (const float4*)g_wcB;
    const float4* __restrict__ woC = (const float4*)g_woC;
    const float4* __restrict__ woD = (const float4*)g_woD;
    const u64*   __restrict__ wcE = (const u64*)g_wcE;

    for (int t = 0; t < SEQ_LEN; ++t) {
        // prefetch x_t early (DRAM latency hidden behind phase B)
        float xr[RPC];
#pragma unroll
        for (int r = 0; r < RPC; ++r)
            xr[r] = x[((size_t)t * BATCH + b0 + r) * OUT_DIM + tid];

        // ---------- Phase B: h_prior = 0.9 h + 0.1 (th@WrT + c@WcT + b_r) ----------
        u64 acc[RPC];
#pragma unroll
        for (int r = 0; r < RPC; ++r) acc[r] = 0ULL;

        {
            float4 buf[8];
#pragma unroll
            for (int u = 0; u < 8; ++u) buf[u] = wrB[u * 256 + tid];
            for (int k2 = 0; k2 < 256; k2 += 8) {
                float4 cur[8];
#pragma unroll
                for (int u = 0; u < 8; ++u) cur[u] = buf[u];
                int kn = (k2 + 8) & 255;           // wraps harmlessly on last iter
#pragma unroll
                for (int u = 0; u < 8; ++u) buf[u] = wrB[(kn + u) * 256 + tid];
#pragma unroll
                for (int u = 0; u < 8; ++u) {
                    int k = (k2 + u) * 2;
                    ulonglong2 ta = *(const ulonglong2*)&s_th2[k * RPC];
                    ulonglong2 tb = *(const ulonglong2*)&s_th2[k * RPC + 2];
                    ulonglong2 tc = *(const ulonglong2*)&s_th2[k * RPC + 4];
                    ulonglong2 td = *(const ulonglong2*)&s_th2[k * RPC + 6];
                    u64 wlo = pack2(cur[u].x, cur[u].y);
                    u64 whi = pack2(cur[u].z, cur[u].w);
                    fma2(acc[0], ta.x, wlo);
                    fma2(acc[1], ta.y, wlo);
                    fma2(acc[2], tb.x, wlo);
                    fma2(acc[3], tb.y, wlo);
                    fma2(acc[0], tc.x, whi);
                    fma2(acc[1], tc.y, whi);
                    fma2(acc[2], td.x, whi);
                    fma2(acc[3], td.y, whi);
                }
            }
        }
#pragma unroll 8
        for (int m2 = 0; m2 < 32; ++m2) {
            float4 w = wcB[m2 * 256 + tid];
            int m = m2 * 2;
            ulonglong2 ca_ = *(const ulonglong2*)&s_c2[m * RPC];
            ulonglong2 cb_ = *(const ulonglong2*)&s_c2[m * RPC + 2];
            ulonglong2 cc_ = *(const ulonglong2*)&s_c2[m * RPC + 4];
            ulonglong2 cd_ = *(const ulonglong2*)&s_c2[m * RPC + 6];
            u64 wlo = pack2(w.x, w.y), whi = pack2(w.z, w.w);
            fma2(acc[0], ca_.x, wlo);
            fma2(acc[1], ca_.y, wlo);
            fma2(acc[2], cb_.x, wlo);
            fma2(acc[3], cb_.y, wlo);
            fma2(acc[0], cc_.x, whi);
            fma2(acc[1], cc_.y, whi);
            fma2(acc[2], cd_.x, whi);
            fma2(acc[3], cd_.y, whi);
        }
#pragma unroll
        for (int r = 0; r < RPC; ++r) {
            float a0, a1; unpack2(acc[r], a0, a1);
            hp0[r] = 0.9f * h0[r] + 0.1f * (a0 + rb0);
            hp1[r] = 0.9f * h1[r] + 0.1f * (a1 + rb1);
            tp0[r] = tanhf(hp0[r]);
            tp1[r] = tanhf(hp1[r]);
        }
        {
            ulonglong2 v0, v1;
            v0.x = pack2(tp0[0], tp0[1]); v0.y = pack2(tp0[2], tp0[3]);
            v1.x = pack2(tp1[0], tp1[1]); v1.y = pack2(tp1[2], tp1[3]);
            *(ulonglong2*)&s_tp2[j0 * 2]     = v0;
            *(ulonglong2*)&s_tp2[j0 * 2 + 2] = v1;
        }
        __syncthreads();

        // ---------- Phase C: err = tp@WoT + b_o - x_t  (o = tid) ----------
        {
            u64 e01 = 0ULL, e23 = 0ULL;
#pragma unroll 8
            for (int j4 = 0; j4 < 128; ++j4) {
                float4 w = woC[j4 * 256 + tid];
                ulonglong2 p0 = *(const ulonglong2*)&s_tp2[(j4 * 4 + 0) * 2];
                ulonglong2 p1 = *(const ulonglong2*)&s_tp2[(j4 * 4 + 1) * 2];
                ulonglong2 p2 = *(const ulonglong2*)&s_tp2[(j4 * 4 + 2) * 2];
                ulonglong2 p3 = *(const ulonglong2*)&s_tp2[(j4 * 4 + 3) * 2];
                u64 w0 = dup2(w.x), w1 = dup2(w.y), w2 = dup2(w.z), w3 = dup2(w.w);
                fma2(e01, p0.x, w0); fma2(e23, p0.y, w0);
                fma2(e01, p1.x, w1); fma2(e23, p1.y, w1);
                fma2(e01, p2.x, w2); fma2(e23, p2.y, w2);
                fma2(e01, p3.x, w3); fma2(e23, p3.y, w3);
            }
            float q0, q1, q2, q3;
            unpack2(e01, q0, q1); unpack2(e23, q2, q3);
            float er0 = (q0 + rbo) - xr[0];
            float er1 = (q1 + rbo) - xr[1];
            float er2 = (q2 + rbo) - xr[2];
            float er3 = (q3 + rbo) - xr[3];
            size_t ob = ((size_t)t * BATCH + b0) * OUT_DIM + tid;
            out[ob]               = er0;
            out[ob + OUT_DIM]     = er1;
            out[ob + 2 * OUT_DIM] = er2;
            out[ob + 3 * OUT_DIM] = er3;
            ulonglong2 s0, s1;
            s0.x = dup2(er0); s0.y = dup2(er1);
            s1.x = dup2(er2); s1.y = dup2(er3);
            *(ulonglong2*)&s_err2[tid * RPC]     = s0;
            *(ulonglong2*)&s_err2[tid * RPC + 2] = s1;
        }
        __syncthreads();

        // ---------- Phase D: h_post = hp - ax (1-tp^2)(err@Wo); th = tanh(h_post) ----------
        {
            u64 g[RPC];
#pragma unroll
            for (int r = 0; r < RPC; ++r) g[r] = 0ULL;
#pragma unroll 8
            for (int o2 = 0; o2 < 128; ++o2) {
                float4 w = woD[o2 * 256 + tid];
                int o = o2 * 2;
                ulonglong2 ea = *(const ulonglong2*)&s_err2[o * RPC];
                ulonglong2 eb = *(const ulonglong2*)&s_err2[o * RPC + 2];
                ulonglong2 ec = *(const ulonglong2*)&s_err2[o * RPC + 4];
                ulonglong2 ed = *(const ulonglong2*)&s_err2[o * RPC + 6];
                u64 wlo = pack2(w.x, w.y), whi = pack2(w.z, w.w);
                fma2(g[0], ea.x, wlo);
                fma2(g[1], ea.y, wlo);
                fma2(g[2], eb.x, wlo);
                fma2(g[3], eb.y, wlo);
                fma2(g[0], ec.x, whi);
                fma2(g[1], ec.y, whi);
                fma2(g[2], ed.x, whi);
                fma2(g[3], ed.y, whi);
            }
            u64 ep[RPC];
#pragma unroll
            for (int r = 0; r < RPC; ++r) {
                float g0, g1; unpack2(g[r], g0, g1);
                float d0 = ALPHA_X * (1.0f - tp0[r] * tp0[r]) * g0;
                float d1 = ALPHA_X * (1.0f - tp1[r] * tp1[r]) * g1;
                h0[r] = hp0[r] - d0;
                h1[r] = hp1[r] - d1;
                ep[r] = pack2(d0, d1);
                s_th2[(j0)     * RPC + r] = dup2(tanhf(h0[r]));
                s_th2[(j0 + 1) * RPC + r] = dup2(tanhf(h1[r]));
            }
            ulonglong2 ev0, ev1;
            ev0.x = ep[0]; ev0.y = ep[1]; ev1.x = ep[2]; ev1.y = ep[3];
            *(ulonglong2*)&s_eh2[tid * RPC]     = ev0;
            *(ulonglong2*)&s_eh2[tid * RPC + 2] = ev1;
        }
        __syncthreads();

        // ---------- Phase E: c -= ah * (eh @ Wc)  (thread = (cm, cr)) ----------
        {
            u64 ca = 0ULL;
#pragma unroll 8
            for (int j2 = 0; j2 < 256; ++j2)
                fma2(ca, s_eh2[j2 * RPC + cr], wcE[j2 * 64 + cm]);
            float cl, ch; unpack2(ca, cl, ch);
            creg = creg - ALPHA_H * (cl + ch);
            s_c2[cm * RPC + cr] = dup2(creg);
        }
        __syncthreads();
    }
}

extern "C" void kernel_launch(void* const* d_in, const int* in_sizes, int n_in,
                              void* d_out, int out_size) {
    const float* x      = (const float*)d_in[0];
    const float* c_init = (const float*)d_in[1];
    const float* h_init = (const float*)d_in[2];
    const float* w_o    = (const float*)d_in[3];
    const float* b_o    = (const float*)d_in[4];
    const float* w_c    = (const float*)d_in[5];
    const float* w_r    = (const float*)d_in[6];
    const float* b_r    = (const float*)d_in[7];
    float* out          = (float*)d_out;

    pack_wrB<<<1024, 256>>>(w_r);
    pack_wcB<<<128,  256>>>(w_c);
    pack_woC<<<512,  256>>>(w_o);
    pack_woD<<<512,  256>>>(w_o);
    pack_wcE<<<128,  256>>>(w_c);

    pc_rnn_kernel<<<NCTA, NT>>>(x, c_init, h_init, b_o, b_r, out);
}

// round 6
// speedup vs baseline: 2.3665x; 1.7288x over previous
#include <cuda_runtime.h>
#include <cuda_bf16.h>

#define SEQ_LEN 512
#define BATCH   256
#define CAUSES  64
#define STATES  512
#define OUT_DIM 256
#define RPC     4
#define NCTA    (BATCH / RPC)
#define NT      512
#define HALFT   256

#define ALPHA_X 0.1f
#define ALPHA_H 0.1f

typedef unsigned long long u64;

// ---------------- packed weight scratch (device globals: allocation-free) ----
// wrP: [k2][jp][4] = {wr[j0][k],wr[j0+1][k],wr[j0][k+1],wr[j0+1][k+1]}  (k=2*k2, j0=2*jp)
__device__ float g_wrP[STATES/2 * STATES * 2];            // 262144
// wcB: {wc[j0][m],wc[j0+1][m],wc[j0][m+1],wc[j0+1][m+1]} over m2 rows
__device__ float g_wcB[CAUSES/2 * STATES * 2];            // 32768
// woC: [j4][o][4] = {wo[o][j4*4+0..3]}
__device__ float g_woC[STATES/4 * OUT_DIM * 4];           // 131072
// woD: [o2][jp][4] = {wo[o][j0],wo[o][j0+1],wo[o+1][j0],wo[o+1][j0+1]}
__device__ float g_woD[OUT_DIM/2 * STATES * 2];           // 131072
// wcE: [j2][m][2] = {wc[2*j2][m], wc[2*j2+1][m]}
__device__ float g_wcE[STATES/2 * CAUSES * 2];            // 32768

// ---------------- packed f32x2 helpers (PTX; ptxas won't auto-fuse) ----
__device__ __forceinline__ u64 dup2(float s) {
    u64 r; asm("mov.b64 %0, {%1, %1};" : "=l"(r) : "f"(s)); return r;
}
__device__ __forceinline__ u64 pack2(float a, float b) {
    u64 r; asm("mov.b64 %0, {%1, %2};" : "=l"(r) : "f"(a), "f"(b)); return r;
}
__device__ __forceinline__ void fma2(u64& d, u64 a, u64 b) {
    asm("fma.rn.f32x2 %0, %1, %2, %3;" : "=l"(d) : "l"(a), "l"(b), "l"(d));
}
__device__ __forceinline__ void unpack2(u64 v, float& lo, float& hi) {
    asm("mov.b64 {%0, %1}, %2;" : "=f"(lo), "=f"(hi) : "l"(v));
}

// ---------------- prologue pack kernels ----------
__global__ void pack_wrB(const float* __restrict__ w) {        // w_r [512][512]
    int idx = blockIdx.x * 256 + threadIdx.x;
    int k2 = idx >> 10, rem = idx & 1023;
    int jp = rem >> 2, c = rem & 3;
    int j = jp * 2 + (c & 1), k = k2 * 2 + (c >> 1);
    g_wrP[idx] = w[j * STATES + k];
}
__global__ void pack_wcB(const float* __restrict__ w) {        // w_c [512][64]
    int idx = blockIdx.x * 256 + threadIdx.x;
    int m2 = idx >> 10, rem = idx & 1023;
    int jp = rem >> 2, c = rem & 3;
    int j = jp * 2 + (c & 1), m = m2 * 2 + (c >> 1);
    g_wcB[idx] = w[j * CAUSES + m];
}
__global__ void pack_woC(const float* __restrict__ w) {        // w_o [256][512]
    int idx = blockIdx.x * 256 + threadIdx.x;
    int j4 = idx >> 10, rem = idx & 1023;
    int o = rem >> 2, jj = rem & 3;
    g_woC[idx] = w[o * STATES + j4 * 4 + jj];
}
__global__ void pack_woD(const float* __restrict__ w) {        // w_o [256][512]
    int idx = blockIdx.x * 256 + threadIdx.x;
    int o2 = idx >> 10, rem = idx & 1023;
    int jp = rem >> 2, c = rem & 3;
    int j = jp * 2 + (c & 1), o = o2 * 2 + (c >> 1);
    g_woD[idx] = w[o * STATES + j];
}
__global__ void pack_wcE(const float* __restrict__ w) {        // w_c [512][64]
    int idx = blockIdx.x * 256 + threadIdx.x;
    int j2 = idx >> 7, rem = idx & 127;
    int m = rem >> 1, jj = rem & 1;
    g_wcE[idx] = w[(j2 * 2 + jj) * CAUSES + m];
}

// ---------------- main persistent recurrence kernel (split-K, 16 warps) ----
__global__ __launch_bounds__(NT, 1)
void pc_rnn_kernel(const float* __restrict__ x,
                   const float* __restrict__ c_init,
                   const float* __restrict__ h_init,
                   const float* __restrict__ b_o,
                   const float* __restrict__ b_r,
                   float* __restrict__ out)
{
    __shared__ u64 s_th2 [STATES  * RPC];     // tanh(h_post) dup'd  [k][r]   16KB
    __shared__ u64 s_tp2 [STATES  * 2];       // tanh(h_prior) pairs [j][rp]   8KB
    __shared__ u64 s_err2[OUT_DIM * RPC];     // error dup'd         [o][r]    8KB
    __shared__ u64 s_eh2 [(STATES/2) * RPC];  // error_h j-pairs     [j2][r]   8KB
    __shared__ u64 s_c2  [CAUSES  * RPC];     // c dup'd             [m][r]    2KB
    __shared__ u64 s_part[HALFT * 4];         // partial exchange              8KB

    const int tid  = threadIdx.x;
    const int lid  = tid & (HALFT - 1);
    const int uppr = tid >> 8;                // 0 = finalizer half, 1 = helper half
    const int b0   = blockIdx.x * RPC;
    const int j0   = lid * 2;

    const float4* __restrict__ wrB = (const float4*)g_wrP;
    const float4* __restrict__ wcB = (const float4*)g_wcB;
    const float4* __restrict__ woC = (const float4*)g_woC;
    const float4* __restrict__ woD = (const float4*)g_woD;
    const u64*    __restrict__ wcE = (const u64*)g_wcE;

    float h0[RPC], h1[RPC], hp0[RPC], hp1[RPC], tp0[RPC], tp1[RPC];
    float rb0 = 0.f, rb1 = 0.f, rbo = 0.f, creg = 0.f;
    const int cm = lid & 63, cr = lid >> 6;

    if (!uppr) {
#pragma unroll
        for (int r = 0; r < RPC; ++r) {
            h0[r] = h_init[(size_t)(b0 + r) * STATES + j0];
            h1[r] = h_init[(size_t)(b0 + r) * STATES + j0 + 1];
            s_th2[(j0)     * RPC + r] = dup2(tanhf(h0[r]));
            s_th2[(j0 + 1) * RPC + r] = dup2(tanhf(h1[r]));
        }
        rb0 = b_r[j0]; rb1 = b_r[j0 + 1];
        rbo = b_o[lid];
        creg = c_init[(size_t)(b0 + cr) * CAUSES + cm];
        s_c2[cm * RPC + cr] = dup2(creg);
    }
    __syncthreads();

    for (int t = 0; t < SEQ_LEN; ++t) {
        // prefetch x_t (finalizer half only; hidden behind phase B)
        float xr[RPC];
        if (!uppr) {
#pragma unroll
            for (int r = 0; r < RPC; ++r)
                xr[r] = x[((size_t)t * BATCH + b0 + r) * OUT_DIM + lid];
        }

        // ---------- Phase B partial: th@WrT + c@WcT over this half's k range ----------
        u64 acc[RPC];
#pragma unroll
        for (int r = 0; r < RPC; ++r) acc[r] = 0ULL;
        {
            const int bk2 = uppr * 128;
#pragma unroll 8
            for (int k2i = 0; k2i < 128; ++k2i) {
                const int k2 = bk2 + k2i;
                float4 w = wrB[k2 * 256 + lid];
                const int k = k2 * 2;
                ulonglong2 ta = *(const ulonglong2*)&s_th2[k * RPC];
                ulonglong2 tb = *(const ulonglong2*)&s_th2[k * RPC + 2];
                ulonglong2 tc = *(const ulonglong2*)&s_th2[k * RPC + 4];
                ulonglong2 td = *(const ulonglong2*)&s_th2[k * RPC + 6];
                u64 wlo = pack2(w.x, w.y), whi = pack2(w.z, w.w);
                fma2(acc[0], ta.x, wlo);
                fma2(acc[1], ta.y, wlo);
                fma2(acc[2], tb.x, wlo);
                fma2(acc[3], tb.y, wlo);
                fma2(acc[0], tc.x, whi);
                fma2(acc[1], tc.y, whi);
                fma2(acc[2], td.x, whi);
                fma2(acc[3], td.y, whi);
            }
            const int bm2 = uppr * 16;
#pragma unroll 8
            for (int m2i = 0; m2i < 16; ++m2i) {
                const int m2 = bm2 + m2i;
                float4 w = wcB[m2 * 256 + lid];
                const int m = m2 * 2;
                ulonglong2 ca_ = *(const ulonglong2*)&s_c2[m * RPC];
                ulonglong2 cb_ = *(const ulonglong2*)&s_c2[m * RPC + 2];
                ulonglong2 cc_ = *(const ulonglong2*)&s_c2[m * RPC + 4];
                ulonglong2 cd_ = *(const ulonglong2*)&s_c2[m * RPC + 6];
                u64 wlo = pack2(w.x, w.y), whi = pack2(w.z, w.w);
                fma2(acc[0], ca_.x, wlo);
                fma2(acc[1], ca_.y, wlo);
                fma2(acc[2], cb_.x, wlo);
                fma2(acc[3], cb_.y, wlo);
                fma2(acc[0], cc_.x, whi);
                fma2(acc[1], cc_.y, whi);
                fma2(acc[2], cd_.x, whi);
                fma2(acc[3], cd_.y, whi);
            }
        }
        if (uppr) {
#pragma unroll
            for (int r = 0; r < RPC; ++r) s_part[lid * 4 + r] = acc[r];
        }
        __syncthreads();

        // ---------- Phase B finalize: h_prior, tanh(h_prior) ----------
        if (!uppr) {
#pragma unroll
            for (int r = 0; r < RPC; ++r) {
                float a0, a1, p0, p1;
                unpack2(acc[r], a0, a1);
                unpack2(s_part[lid * 4 + r], p0, p1);
                a0 += p0; a1 += p1;
                hp0[r] = 0.9f * h0[r] + 0.1f * (a0 + rb0);
                hp1[r] = 0.9f * h1[r] + 0.1f * (a1 + rb1);
                tp0[r] = tanhf(hp0[r]);
                tp1[r] = tanhf(hp1[r]);
            }
            ulonglong2 v0, v1;
            v0.x = pack2(tp0[0], tp0[1]); v0.y = pack2(tp0[2], tp0[3]);
            v1.x = pack2(tp1[0], tp1[1]); v1.y = pack2(tp1[2], tp1[3]);
            *(ulonglong2*)&s_tp2[j0 * 2]     = v0;
            *(ulonglong2*)&s_tp2[j0 * 2 + 2] = v1;
        }
        __syncthreads();

        // ---------- Phase C partial: tp@WoT over this half's j range (o = lid) ----------
        {
            u64 e01 = 0ULL, e23 = 0ULL;
            const int bj4 = uppr * 64;
#pragma unroll 8
            for (int j4i = 0; j4i < 64; ++j4i) {
                const int j4 = bj4 + j4i;
                float4 w = woC[j4 * 256 + lid];
                ulonglong2 p0 = *(const ulonglong2*)&s_tp2[(j4 * 4 + 0) * 2];
                ulonglong2 p1 = *(const ulonglong2*)&s_tp2[(j4 * 4 + 1) * 2];
                ulonglong2 p2 = *(const ulonglong2*)&s_tp2[(j4 * 4 + 2) * 2];
                ulonglong2 p3 = *(const ulonglong2*)&s_tp2[(j4 * 4 + 3) * 2];
                u64 w0 = dup2(w.x), w1 = dup2(w.y), w2 = dup2(w.z), w3 = dup2(w.w);
                fma2(e01, p0.x, w0); fma2(e23, p0.y, w0);
                fma2(e01, p1.x, w1); fma2(e23, p1.y, w1);
                fma2(e01, p2.x, w2); fma2(e23, p2.y, w2);
                fma2(e01, p3.x, w3); fma2(e23, p3.y, w3);
            }
            if (uppr) {
                s_part[lid * 4]     = e01;
                s_part[lid * 4 + 1] = e23;
            } else {
                acc[0] = e01; acc[1] = e23;   // stash in acc regs
            }
        }
        __syncthreads();

        // ---------- Phase C finalize: err = pred - x_t; out + s_err2 ----------
        if (!uppr) {
            float q0, q1, q2, q3, u0, u1, u2, u3;
            unpack2(acc[0], q0, q1); unpack2(acc[1], q2, q3);
            unpack2(s_part[lid * 4], u0, u1); unpack2(s_part[lid * 4 + 1], u2, u3);
            float er0 = (q0 + u0 + rbo) - xr[0];
            float er1 = (q1 + u1 + rbo) - xr[1];
            float er2 = (q2 + u2 + rbo) - xr[2];
            float er3 = (q3 + u3 + rbo) - xr[3];
            size_t ob = ((size_t)t * BATCH + b0) * OUT_DIM + lid;
            out[ob]               = er0;
            out[ob + OUT_DIM]     = er1;
            out[ob + 2 * OUT_DIM] = er2;
            out[ob + 3 * OUT_DIM] = er3;
            ulonglong2 s0, s1;
            s0.x = dup2(er0); s0.y = dup2(er1);
            s1.x = dup2(er2); s1.y = dup2(er3);
            *(ulonglong2*)&s_err2[lid * RPC]     = s0;
            *(ulonglong2*)&s_err2[lid * RPC + 2] = s1;
        }
        __syncthreads();

        // ---------- Phase D partial: err@Wo over this half's o range ----------
        {
            u64 g[RPC];
#pragma unroll
            for (int r = 0; r < RPC; ++r) g[r] = 0ULL;
            const int bo2 = uppr * 64;
#pragma unroll 8
            for (int o2i = 0; o2i < 64; ++o2i) {
                const int o2 = bo2 + o2i;
                float4 w = woD[o2 * 256 + lid];
                const int o = o2 * 2;
                ulonglong2 ea = *(const ulonglong2*)&s_err2[o * RPC];
                ulonglong2 eb = *(const ulonglong2*)&s_err2[o * RPC + 2];
                ulonglong2 ec = *(const ulonglong2*)&s_err2[o * RPC + 4];
                ulonglong2 ed = *(const ulonglong2*)&s_err2[o * RPC + 6];
                u64 wlo = pack2(w.x, w.y), whi = pack2(w.z, w.w);
                fma2(g[0], ea.x, wlo);
                fma2(g[1], ea.y, wlo);
                fma2(g[2], eb.x, wlo);
                fma2(g[3], eb.y, wlo);
                fma2(g[0], ec.x, whi);
                fma2(g[1], ec.y, whi);
                fma2(g[2], ed.x, whi);
                fma2(g[3], ed.y, whi);
            }
            if (uppr) {
#pragma unroll
                for (int r = 0; r < RPC; ++r) s_part[lid * 4 + r] = g[r];
            } else {
#pragma unroll
                for (int r = 0; r < RPC; ++r) acc[r] = g[r];
            }
        }
        __syncthreads();

        // ---------- Phase D finalize: h_post, th = tanh(h_post), eh ----------
        if (!uppr) {
            u64 ep[RPC];
#pragma unroll
            for (int r = 0; r < RPC; ++r) {
                float g0, g1, p0, p1;
                unpack2(acc[r], g0, g1);
                unpack2(s_part[lid * 4 + r], p0, p1);
                g0 += p0; g1 += p1;
                float d0 = ALPHA_X * (1.0f - tp0[r] * tp0[r]) * g0;
                float d1 = ALPHA_X * (1.0f - tp1[r] * tp1[r]) * g1;
                h0[r] = hp0[r] - d0;
                h1[r] = hp1[r] - d1;
                ep[r] = pack2(d0, d1);
                s_th2[(j0)     * RPC + r] = dup2(tanhf(h0[r]));
                s_th2[(j0 + 1) * RPC + r] = dup2(tanhf(h1[r]));
            }
            ulonglong2 ev0, ev1;
            ev0.x = ep[0]; ev0.y = ep[1]; ev1.x = ep[2]; ev1.y = ep[3];
            *(ulonglong2*)&s_eh2[lid * RPC]     = ev0;
            *(ulonglong2*)&s_eh2[lid * RPC + 2] = ev1;
        }
        __syncthreads();

        // ---------- Phase E partial: eh@Wc over this half's j range ----------
        {
            u64 ca = 0ULL;
            const int bj2 = uppr * 128;
#pragma unroll 8
            for (int j2i = 0; j2i < 128; ++j2i) {
                const int j2 = bj2 + j2i;
                fma2(ca, s_eh2[j2 * RPC + cr], wcE[j2 * 64 + cm]);
            }
            if (uppr) s_part[lid] = ca;
            else      acc[0] = ca;
        }
        __syncthreads();

        // ---------- Phase E finalize: c update ----------
        if (!uppr) {
            float cl, ch, pl, ph;
            unpack2(acc[0], cl, ch);
            unpack2(s_part[lid], pl, ph);
            creg = creg - ALPHA_H * (cl + ch + pl + ph);
            s_c2[cm * RPC + cr] = dup2(creg);
        }
        __syncthreads();
    }
}

extern "C" void kernel_launch(void* const* d_in, const int* in_sizes, int n_in,
                              void* d_out, int out_size) {
    const float* x      = (const float*)d_in[0];
    const float* c_init = (const float*)d_in[1];
    const float* h_init = (const float*)d_in[2];
    const float* w_o    = (const float*)d_in[3];
    const float* b_o    = (const float*)d_in[4];
    const float* w_c    = (const float*)d_in[5];
    const float* w_r    = (const float*)d_in[6];
    const float* b_r    = (const float*)d_in[7];
    float* out          = (float*)d_out;

    pack_wrB<<<1024, 256>>>(w_r);
    pack_wcB<<<128,  256>>>(w_c);
    pack_woC<<<512,  256>>>(w_o);
    pack_woD<<<512,  256>>>(w_o);
    pack_wcE<<<128,  256>>>(w_c);

    pc_rnn_kernel<<<NCTA, NT>>>(x, c_init, h_init, b_o, b_r, out);
}